// round 7
// baseline (speedup 1.0000x reference)
#include <cuda_runtime.h>
#include <cuda_fp16.h>
#include <cstddef>
#include <cstdint>

#define NN 50000
#define EE 800000
#define HEADS 4
#define HIDD 64
#define FW 256      // HEADS*HIDD
#define NEG 0.2f

// ---------------- scratch (static device globals; no allocation) ----------------
__device__ __half2 g_featH[(size_t)NN * (FW / 2)];
__device__ float g_bufA[(size_t)NN * FW];
__device__ float g_bufB[(size_t)NN * FW];
__device__ float g_el[NN * 4];
__device__ float g_er[NN * 4];
__device__ float g_wproj[8 * 256];
__device__ float g_feat4[NN * 8];
__device__ float g_res4[NN * 8];
__device__ float g_el4[NN * 4];
__device__ float g_er4[NN * 4];
__device__ int g_count[NN];
__device__ int g_rowstart[NN + 1];
__device__ int g_rowfill[NN];
__device__ int g_csrsrc[EE];

// ---------------- CSR build ----------------
__global__ void zero_counts_kernel() {
    int i = blockIdx.x * blockDim.x + threadIdx.x;
    if (i < NN) g_count[i] = 0;
}

__global__ void hist_kernel(const int* __restrict__ dst) {
    int i = blockIdx.x * blockDim.x + threadIdx.x;
    if (i < EE) atomicAdd(&g_count[dst[i]], 1);
}

// shfl-based single-block scan (1024 threads)
__global__ void scan_kernel() {
    __shared__ int warpsum[32];
    __shared__ int carry;
    int t = threadIdx.x;
    int lane = t & 31, wid = t >> 5;
    if (t == 0) { carry = 0; g_rowstart[0] = 0; }
    __syncthreads();
    for (int base = 0; base < NN; base += 1024) {
        int i = base + t;
        int v = (i < NN) ? g_count[i] : 0;
        int x = v;
#pragma unroll
        for (int off = 1; off < 32; off <<= 1) {
            int y = __shfl_up_sync(0xffffffffu, x, off);
            if (lane >= off) x += y;
        }
        if (lane == 31) warpsum[wid] = x;
        __syncthreads();
        if (wid == 0) {
            int s = warpsum[lane];
#pragma unroll
            for (int off = 1; off < 32; off <<= 1) {
                int y = __shfl_up_sync(0xffffffffu, s, off);
                if (lane >= off) s += y;
            }
            warpsum[lane] = s;
        }
        __syncthreads();
        int incl = x + (wid ? warpsum[wid - 1] : 0) + carry;
        if (i < NN) {
            g_rowstart[i + 1] = incl;
            g_rowfill[i] = incl - v;
        }
        __syncthreads();
        if (t == 1023) carry = incl;
        __syncthreads();
    }
}

__global__ void scatter_kernel(const int* __restrict__ src, const int* __restrict__ dst) {
    int i = blockIdx.x * blockDim.x + threadIdx.x;
    if (i < EE) {
        int pos = atomicAdd(&g_rowfill[dst[i]], 1);
        g_csrsrc[pos] = src[i];
    }
}

// ---------------- attention projection fold: Wlr[j][k] = sum_o W[h*64+o,k]*v[h,o] ----------------
// grid 8 (j = isR*4 + h), block K threads
__global__ void wproj_kernel(const float* __restrict__ W, const float* __restrict__ al,
                             const float* __restrict__ ar, int K) {
    int j = blockIdx.x;
    int h = j & 3;
    const float* v = (j >= 4) ? ar : al;
    int k = threadIdx.x;
    float s = 0.f;
#pragma unroll 8
    for (int o = 0; o < 64; o++)
        s += W[(size_t)(h * 64 + o) * K + k] * v[h * 64 + o];
    g_wproj[j * 256 + k] = s;
}

// el/er from layer input A: [M,8] = A[M,K] @ Wlr^T
template<int K>
__global__ void __launch_bounds__(256) elproj_kernel(const float* __restrict__ A,
                                                     float* __restrict__ el,
                                                     float* __restrict__ er, int M) {
    __shared__ float sw[8][K];
    int t = threadIdx.x;
    for (int i = t; i < 8 * K; i += 256) sw[i / K][i % K] = g_wproj[(i / K) * 256 + (i % K)];
    __syncthreads();
    int nl = t >> 3, j = t & 7;
    int n = blockIdx.x * 32 + nl;
    if (n >= M) return;
    const float4* a = (const float4*)(A + (size_t)n * K);
    const float4* w = (const float4*)&sw[j][0];
    float s = 0.f;
#pragma unroll 8
    for (int k = 0; k < K / 4; k++) {
        float4 av = a[k], wv = w[k];
        s += av.x * wv.x + av.y * wv.y + av.z * wv.z + av.w * wv.w;
    }
    if (j < 4) el[n * 4 + j] = s;
    else       er[n * 4 + (j - 4)] = s;
}

// ---------------- tf32 tensor-core GEMM: CH[M,256](fp16) = A[M,K] * B[256,K]^T ----------------
template<int K>
__global__ void __launch_bounds__(256, 2) gemm_tc_kernel(const float* __restrict__ A,
                                                         const float* __restrict__ B,
                                                         __half2* __restrict__ CH, int M) {
    __shared__ float As[128][36];
    __shared__ float Bs[128][36];
    int t = threadIdx.x;
    int lane = t & 31;
    int warp = t >> 5;
    int wm = warp & 3;
    int wn = warp >> 2;
    int g = lane >> 2;
    int tg = lane & 3;
    int m0 = blockIdx.x * 128;
    int n0 = blockIdx.y * 128;

    float c[2][8][4];
#pragma unroll
    for (int mf = 0; mf < 2; mf++)
#pragma unroll
        for (int nf = 0; nf < 8; nf++)
#pragma unroll
            for (int k = 0; k < 4; k++) c[mf][nf][k] = 0.f;

    for (int kt = 0; kt < K; kt += 32) {
#pragma unroll
        for (int j = 0; j < 4; j++) {
            int idx = t + j * 256;
            int row = idx >> 3;
            int kq = idx & 7;
            const float* gp = A + (size_t)(m0 + row) * K + kt + kq * 4;
            float4 v = (m0 + row < M) ? *(const float4*)gp : make_float4(0.f, 0.f, 0.f, 0.f);
            uint4 u;
            asm("cvt.rna.tf32.f32 %0, %1;" : "=r"(u.x) : "f"(v.x));
            asm("cvt.rna.tf32.f32 %0, %1;" : "=r"(u.y) : "f"(v.y));
            asm("cvt.rna.tf32.f32 %0, %1;" : "=r"(u.z) : "f"(v.z));
            asm("cvt.rna.tf32.f32 %0, %1;" : "=r"(u.w) : "f"(v.w));
            *(uint4*)&As[row][kq * 4] = u;
            const float* gq = B + (size_t)(n0 + row) * K + kt + kq * 4;
            float4 w = *(const float4*)gq;
            uint4 uw;
            asm("cvt.rna.tf32.f32 %0, %1;" : "=r"(uw.x) : "f"(w.x));
            asm("cvt.rna.tf32.f32 %0, %1;" : "=r"(uw.y) : "f"(w.y));
            asm("cvt.rna.tf32.f32 %0, %1;" : "=r"(uw.z) : "f"(w.z));
            asm("cvt.rna.tf32.f32 %0, %1;" : "=r"(uw.w) : "f"(w.w));
            *(uint4*)&Bs[row][kq * 4] = uw;
        }
        __syncthreads();

#pragma unroll
        for (int ks = 0; ks < 32; ks += 8) {
            uint32_t a[2][4], b[8][2];
#pragma unroll
            for (int mf = 0; mf < 2; mf++) {
                int r = wm * 32 + mf * 16 + g;
                a[mf][0] = __float_as_uint(As[r][ks + tg]);
                a[mf][1] = __float_as_uint(As[r + 8][ks + tg]);
                a[mf][2] = __float_as_uint(As[r][ks + tg + 4]);
                a[mf][3] = __float_as_uint(As[r + 8][ks + tg + 4]);
            }
#pragma unroll
            for (int nf = 0; nf < 8; nf++) {
                int col = wn * 64 + nf * 8 + g;
                b[nf][0] = __float_as_uint(Bs[col][ks + tg]);
                b[nf][1] = __float_as_uint(Bs[col][ks + tg + 4]);
            }
#pragma unroll
            for (int mf = 0; mf < 2; mf++)
#pragma unroll
                for (int nf = 0; nf < 8; nf++) {
                    asm volatile(
                        "mma.sync.aligned.m16n8k8.row.col.f32.tf32.tf32.f32 "
                        "{%0,%1,%2,%3}, {%4,%5,%6,%7}, {%8,%9}, {%0,%1,%2,%3};"
                        : "+f"(c[mf][nf][0]), "+f"(c[mf][nf][1]),
                          "+f"(c[mf][nf][2]), "+f"(c[mf][nf][3])
                        : "r"(a[mf][0]), "r"(a[mf][1]), "r"(a[mf][2]), "r"(a[mf][3]),
                          "r"(b[nf][0]), "r"(b[nf][1]));
                }
        }
        __syncthreads();
    }

#pragma unroll
    for (int mf = 0; mf < 2; mf++) {
        int r0 = m0 + wm * 32 + mf * 16 + g;
#pragma unroll
        for (int nf = 0; nf < 8; nf++) {
            int col = n0 + wn * 64 + nf * 8 + tg * 2;
            if (r0 < M)
                CH[(size_t)r0 * (FW / 2) + (col >> 1)] = __floats2half2_rn(c[mf][nf][0], c[mf][nf][1]);
            if (r0 + 8 < M)
                CH[(size_t)(r0 + 8) * (FW / 2) + (col >> 1)] = __floats2half2_rn(c[mf][nf][2], c[mf][nf][3]);
        }
    }
}

__device__ __forceinline__ float lrelu(float x) { return x >= 0.f ? x : NEG * x; }
__device__ __forceinline__ float comp4(float4 v, int i) {
    return i == 0 ? v.x : (i == 1 ? v.y : (i == 2 ? v.z : v.w));
}

// ---------------- aggregation, OUT=64 (layers 1-3): warp per dst node, single pass ----------------
__global__ void __launch_bounds__(256) agg64_kernel(const __half2* __restrict__ featH,
                                                    const float* __restrict__ el,
                                                    const float* __restrict__ er,
                                                    const float* __restrict__ resid,
                                                    const float* __restrict__ bias,
                                                    float* __restrict__ out) {
    __shared__ float4 s_ee[8][32];
    __shared__ int s_src[8][32];
    int warp = threadIdx.x >> 5;
    int n = (blockIdx.x * blockDim.x + threadIdx.x) >> 5;
    int lane = threadIdx.x & 31;
    if (n >= NN) return;
    int beg = g_rowstart[n], end = g_rowstart[n + 1];
    float4 erv = ((const float4*)er)[n];

    float acc[8];
#pragma unroll
    for (int k = 0; k < 8; k++) acc[k] = 0.f;
    float4 den = make_float4(0.f, 0.f, 0.f, 0.f);
    int hsel = lane >> 3;
    const float4* fH = (const float4*)featH;   // 16B per node-quarter

    for (int c = beg; c < end; c += 32) {
        // phase a: edge-parallel weight computation (no max pass: |e| is small)
        int i = c + lane;
        float4 ee = make_float4(0.f, 0.f, 0.f, 0.f);
        int s = 0;
        if (i < end) {
            s = g_csrsrc[i];
            float4 e = ((const float4*)el)[s];
            ee.x = __expf(lrelu(e.x + erv.x));
            ee.y = __expf(lrelu(e.y + erv.y));
            ee.z = __expf(lrelu(e.z + erv.z));
            ee.w = __expf(lrelu(e.w + erv.w));
            den.x += ee.x; den.y += ee.y; den.z += ee.z; den.w += ee.w;
        }
        s_ee[warp][lane] = ee;
        s_src[warp][lane] = s;
        __syncwarp();
        int cnt = min(end - c, 32);
        const float* wsm = (const float*)&s_ee[warp][0];
        int j = 0;
        for (; j + 4 <= cnt; j += 4) {
            int s0 = s_src[warp][j + 0];
            int s1 = s_src[warp][j + 1];
            int s2 = s_src[warp][j + 2];
            int s3 = s_src[warp][j + 3];
            float4 h0 = fH[(size_t)s0 * 32 + lane];
            float4 h1 = fH[(size_t)s1 * 32 + lane];
            float4 h2 = fH[(size_t)s2 * 32 + lane];
            float4 h3 = fH[(size_t)s3 * 32 + lane];
            float w0 = wsm[(j + 0) * 4 + hsel];
            float w1 = wsm[(j + 1) * 4 + hsel];
            float w2 = wsm[(j + 2) * 4 + hsel];
            float w3 = wsm[(j + 3) * 4 + hsel];
#pragma unroll
            for (int q = 0; q < 4; q++) {
                float4 hv = (q == 0) ? h0 : (q == 1) ? h1 : (q == 2) ? h2 : h3;
                float w  = (q == 0) ? w0 : (q == 1) ? w1 : (q == 2) ? w2 : w3;
                float2 f0 = __half22float2(((const __half2*)&hv)[0]);
                float2 f1 = __half22float2(((const __half2*)&hv)[1]);
                float2 f2 = __half22float2(((const __half2*)&hv)[2]);
                float2 f3 = __half22float2(((const __half2*)&hv)[3]);
                acc[0] += w * f0.x; acc[1] += w * f0.y;
                acc[2] += w * f1.x; acc[3] += w * f1.y;
                acc[4] += w * f2.x; acc[5] += w * f2.y;
                acc[6] += w * f3.x; acc[7] += w * f3.y;
            }
        }
        for (; j < cnt; j++) {
            int sj = s_src[warp][j];
            float w = wsm[j * 4 + hsel];
            float4 hv = fH[(size_t)sj * 32 + lane];
            float2 f0 = __half22float2(((const __half2*)&hv)[0]);
            float2 f1 = __half22float2(((const __half2*)&hv)[1]);
            float2 f2 = __half22float2(((const __half2*)&hv)[2]);
            float2 f3 = __half22float2(((const __half2*)&hv)[3]);
            acc[0] += w * f0.x; acc[1] += w * f0.y;
            acc[2] += w * f1.x; acc[3] += w * f1.y;
            acc[4] += w * f2.x; acc[5] += w * f2.y;
            acc[6] += w * f3.x; acc[7] += w * f3.y;
        }
        __syncwarp();
    }

#pragma unroll
    for (int off = 16; off >= 1; off >>= 1) {
        den.x += __shfl_xor_sync(0xffffffffu, den.x, off);
        den.y += __shfl_xor_sync(0xffffffffu, den.y, off);
        den.z += __shfl_xor_sync(0xffffffffu, den.z, off);
        den.w += __shfl_xor_sync(0xffffffffu, den.w, off);
    }
    float dh = comp4(den, hsel);
    float inv = (end > beg) ? 1.f / dh : 0.f;
    int base = n * FW + lane * 8;
    float o[8];
#pragma unroll
    for (int k = 0; k < 8; k++) {
        float v = acc[k] * inv + bias[lane * 8 + k];
        if (resid) v += resid[base + k];
        o[k] = v > 0.f ? v : (__expf(v) - 1.f);  // ELU
    }
    *(float4*)(out + base) = make_float4(o[0], o[1], o[2], o[3]);
    *(float4*)(out + base + 4) = make_float4(o[4], o[5], o[6], o[7]);
}

// ---------------- layer 4 GEMMs: feat4 = h*W4^T, res4 = h*resW4^T (NC=8) ----------------
__global__ void __launch_bounds__(256) gemm4_kernel(const float* __restrict__ A,
                                                    const float* __restrict__ W,
                                                    const float* __restrict__ R,
                                                    float* __restrict__ F,
                                                    float* __restrict__ Rv, int M) {
    __shared__ float sW[8 * 260];
    __shared__ float sR[8 * 260];
    int t = threadIdx.x;
    for (int i = t; i < 2048; i += 256) {
        int j = i >> 8, k = i & 255;
        sW[j * 260 + k] = W[i];
        sR[j * 260 + k] = R[i];
    }
    __syncthreads();
    int nl = t >> 3, j = t & 7;
    int n = blockIdx.x * 32 + nl;
    if (n >= M) return;
    const float4* a = (const float4*)(A + (size_t)n * 256);
    const float4* w = (const float4*)(sW + j * 260);
    const float4* r = (const float4*)(sR + j * 260);
    float s1 = 0.f, s2 = 0.f;
#pragma unroll 8
    for (int k = 0; k < 64; k++) {
        float4 av = a[k];
        float4 wv = w[k];
        float4 rv = r[k];
        s1 += av.x * wv.x + av.y * wv.y + av.z * wv.z + av.w * wv.w;
        s2 += av.x * rv.x + av.y * rv.y + av.z * rv.z + av.w * rv.w;
    }
    F[(size_t)n * 8 + j] = s1;
    Rv[(size_t)n * 8 + j] = s2;
}

__global__ void elr4_kernel(const float* __restrict__ feat4, const float* __restrict__ al4,
                            const float* __restrict__ ar4, float* __restrict__ el4,
                            float* __restrict__ er4) {
    int n = blockIdx.x * blockDim.x + threadIdx.x;
    if (n >= NN) return;
    float4 f0 = ((const float4*)feat4)[n * 2];
    float4 f1 = ((const float4*)feat4)[n * 2 + 1];
    float4 a0 = ((const float4*)al4)[0], a1 = ((const float4*)al4)[1];
    float4 r0 = ((const float4*)ar4)[0], r1 = ((const float4*)ar4)[1];
    float4 el, er;
    el.x = f0.x * a0.x + f0.y * a0.y;  er.x = f0.x * r0.x + f0.y * r0.y;
    el.y = f0.z * a0.z + f0.w * a0.w;  er.y = f0.z * r0.z + f0.w * r0.w;
    el.z = f1.x * a1.x + f1.y * a1.y;  er.z = f1.x * r1.x + f1.y * r1.y;
    el.w = f1.z * a1.z + f1.w * a1.w;  er.w = f1.z * r1.z + f1.w * r1.w;
    ((float4*)el4)[n] = el;
    ((float4*)er4)[n] = er;
}

// ---------------- layer 4 aggregation + softmax + head-mean (single pass) ----------------
__global__ void agg4_kernel(const float* __restrict__ feat4, const float* __restrict__ el4,
                            const float* __restrict__ er4, const float* __restrict__ res4,
                            const float* __restrict__ b4, float* __restrict__ out) {
    int n = (blockIdx.x * blockDim.x + threadIdx.x) >> 5;
    int lane = threadIdx.x & 31;
    if (n >= NN) return;
    int beg = g_rowstart[n], end = g_rowstart[n + 1];
    float4 erv = ((const float4*)er4)[n];

    float acc = 0.f;
    float4 den = make_float4(0.f, 0.f, 0.f, 0.f);
    int h = (lane >> 1) & 3;  // lane<8: lane = h*2 + c
    for (int i = beg; i < end; i++) {
        int s = g_csrsrc[i];
        float4 e = ((const float4*)el4)[s];
        float4 ee;
        ee.x = __expf(lrelu(e.x + erv.x));
        ee.y = __expf(lrelu(e.y + erv.y));
        ee.z = __expf(lrelu(e.z + erv.z));
        ee.w = __expf(lrelu(e.w + erv.w));
        den.x += ee.x; den.y += ee.y; den.z += ee.z; den.w += ee.w;
        if (lane < 8) acc += comp4(ee, h) * feat4[(size_t)s * 8 + lane];
    }

    float v = 0.f;
    if (lane < 8) {
        float dh = comp4(den, h);
        v = (end > beg ? acc / dh : 0.f) + res4[n * 8 + lane] + b4[lane];
    }
    float other = __shfl_xor_sync(0xffffffffu, v, 1);
    float mx = fmaxf(v, other);
    float ev = __expf(v - mx);
    float eo = __expf(other - mx);
    float sm = ev / (ev + eo);
    sm += __shfl_xor_sync(0xffffffffu, sm, 4);
    sm += __shfl_xor_sync(0xffffffffu, sm, 2);
    if (lane < 2) out[n * 2 + lane] = sm * 0.25f;
}

// ---------------- host ----------------
extern "C" void kernel_launch(void* const* d_in, const int* in_sizes, int n_in,
                              void* d_out, int out_size) {
    const float* x    = (const float*)d_in[0];
    const int*   src  = (const int*)d_in[1];
    const int*   dst  = (const int*)d_in[2];
    const float* W1   = (const float*)d_in[3];
    const float* al1  = (const float*)d_in[4];
    const float* ar1  = (const float*)d_in[5];
    const float* b1   = (const float*)d_in[6];
    const float* W2   = (const float*)d_in[7];
    const float* al2  = (const float*)d_in[8];
    const float* ar2  = (const float*)d_in[9];
    const float* b2   = (const float*)d_in[10];
    const float* W3   = (const float*)d_in[11];
    const float* al3  = (const float*)d_in[12];
    const float* ar3  = (const float*)d_in[13];
    const float* b3   = (const float*)d_in[14];
    const float* W4   = (const float*)d_in[15];
    const float* al4  = (const float*)d_in[16];
    const float* ar4  = (const float*)d_in[17];
    const float* b4   = (const float*)d_in[18];
    const float* rW4  = (const float*)d_in[19];
    float* out = (float*)d_out;

    void *p_featH, *p_bufA, *p_bufB, *p_el, *p_er, *p_f4, *p_r4, *p_el4, *p_er4;
    cudaGetSymbolAddress(&p_featH, g_featH);
    cudaGetSymbolAddress(&p_bufA, g_bufA);
    cudaGetSymbolAddress(&p_bufB, g_bufB);
    cudaGetSymbolAddress(&p_el, g_el);
    cudaGetSymbolAddress(&p_er, g_er);
    cudaGetSymbolAddress(&p_f4, g_feat4);
    cudaGetSymbolAddress(&p_r4, g_res4);
    cudaGetSymbolAddress(&p_el4, g_el4);
    cudaGetSymbolAddress(&p_er4, g_er4);
    __half2* featH = (__half2*)p_featH;
    float* bufA = (float*)p_bufA;
    float* bufB = (float*)p_bufB;
    float* el   = (float*)p_el;
    float* er   = (float*)p_er;
    float* f4   = (float*)p_f4;
    float* r4   = (float*)p_r4;
    float* el4  = (float*)p_el4;
    float* er4  = (float*)p_er4;

    const int TB = 256;
    int nodeBlocks = (NN + TB - 1) / TB;
    int edgeBlocks = (EE + TB - 1) / TB;
    int warpBlocks = (NN * 32 + TB - 1) / TB;
    int projBlocks = (NN + 31) / 32;
    dim3 gemmGrid((NN + 127) / 128, 2);

    // --- CSR build (reused by all layers) ---
    zero_counts_kernel<<<nodeBlocks, TB>>>();
    hist_kernel<<<edgeBlocks, TB>>>(dst);
    scan_kernel<<<1, 1024>>>();
    scatter_kernel<<<edgeBlocks, TB>>>(src, dst);

    // --- layer 1: IN=128 -> 256, no residual ---
    gemm_tc_kernel<128><<<gemmGrid, TB>>>(x, W1, featH, NN);
    wproj_kernel<<<8, 128>>>(W1, al1, ar1, 128);
    elproj_kernel<128><<<projBlocks, TB>>>(x, el, er, NN);
    agg64_kernel<<<warpBlocks, TB>>>(featH, el, er, nullptr, b1, bufA);

    // --- layer 2: 256 -> 256, identity residual ---
    gemm_tc_kernel<256><<<gemmGrid, TB>>>(bufA, W2, featH, NN);
    wproj_kernel<<<8, 256>>>(W2, al2, ar2, 256);
    elproj_kernel<256><<<projBlocks, TB>>>(bufA, el, er, NN);
    agg64_kernel<<<warpBlocks, TB>>>(featH, el, er, bufA, b2, bufB);

    // --- layer 3: 256 -> 256, identity residual ---
    gemm_tc_kernel<256><<<gemmGrid, TB>>>(bufB, W3, featH, NN);
    wproj_kernel<<<8, 256>>>(W3, al3, ar3, 256);
    elproj_kernel<256><<<projBlocks, TB>>>(bufB, el, er, NN);
    agg64_kernel<<<warpBlocks, TB>>>(featH, el, er, bufB, b3, bufA);

    // --- layer 4: 256 -> 8, fc residual, softmax + head-mean ---
    gemm4_kernel<<<(NN + 31) / 32, TB>>>(bufA, W4, rW4, f4, r4, NN);
    elr4_kernel<<<nodeBlocks, TB>>>(f4, al4, ar4, el4, er4);
    agg4_kernel<<<warpBlocks, TB>>>(f4, el4, er4, r4, b4, out);
}

// round 9
// speedup vs baseline: 1.3589x; 1.3589x over previous
#include <cuda_runtime.h>
#include <cuda_fp16.h>
#include <cstddef>
#include <cstdint>

#define NN 50000
#define EE 800000
#define HEADS 4
#define HIDD 64
#define FW 256      // HEADS*HIDD
#define NEG 0.2f

// ---------------- scratch (static device globals; no allocation) ----------------
__device__ float g_feat[(size_t)NN * FW];
__device__ __half2 g_featH[(size_t)NN * (FW / 2)];
__device__ float g_bufA[(size_t)NN * FW];
__device__ float g_bufB[(size_t)NN * FW];
__device__ float g_el[NN * 4];
__device__ float g_er[NN * 4];
__device__ float g_feat4[NN * 8];
__device__ float g_res4[NN * 8];
__device__ float g_el4[NN * 4];
__device__ float g_er4[NN * 4];
__device__ int g_count[NN];
__device__ int g_rowstart[NN + 1];
__device__ int g_rowfill[NN];
__device__ int g_csrsrc[EE];

// ---------------- CSR build ----------------
__global__ void zero_counts_kernel() {
    int i = blockIdx.x * blockDim.x + threadIdx.x;
    if (i < NN) g_count[i] = 0;
}

__global__ void hist_kernel(const int* __restrict__ dst) {
    int i = blockIdx.x * blockDim.x + threadIdx.x;
    if (i < EE) atomicAdd(&g_count[dst[i]], 1);
}

// shfl-based single-block scan (1024 threads)
__global__ void scan_kernel() {
    __shared__ int warpsum[32];
    __shared__ int carry;
    int t = threadIdx.x;
    int lane = t & 31, wid = t >> 5;
    if (t == 0) { carry = 0; g_rowstart[0] = 0; }
    __syncthreads();
    for (int base = 0; base < NN; base += 1024) {
        int i = base + t;
        int v = (i < NN) ? g_count[i] : 0;
        int x = v;
#pragma unroll
        for (int off = 1; off < 32; off <<= 1) {
            int y = __shfl_up_sync(0xffffffffu, x, off);
            if (lane >= off) x += y;
        }
        if (lane == 31) warpsum[wid] = x;
        __syncthreads();
        if (wid == 0) {
            int s = warpsum[lane];
#pragma unroll
            for (int off = 1; off < 32; off <<= 1) {
                int y = __shfl_up_sync(0xffffffffu, s, off);
                if (lane >= off) s += y;
            }
            warpsum[lane] = s;
        }
        __syncthreads();
        int incl = x + (wid ? warpsum[wid - 1] : 0) + carry;
        if (i < NN) {
            g_rowstart[i + 1] = incl;
            g_rowfill[i] = incl - v;
        }
        __syncthreads();
        if (t == 1023) carry = incl;
        __syncthreads();
    }
}

__global__ void scatter_kernel(const int* __restrict__ src, const int* __restrict__ dst) {
    int i = blockIdx.x * blockDim.x + threadIdx.x;
    if (i < EE) {
        int pos = atomicAdd(&g_rowfill[dst[i]], 1);
        g_csrsrc[pos] = src[i];
    }
}

// ---------------- tf32 tensor-core GEMM: C[M,256] = A[M,K] * B[256,K]^T ----------------
// Also emits an fp16 copy (CH) of C for the gather path.
template<int K>
__global__ void __launch_bounds__(256, 2) gemm_tc_kernel(const float* __restrict__ A,
                                                         const float* __restrict__ B,
                                                         float* __restrict__ C,
                                                         __half2* __restrict__ CH, int M) {
    __shared__ float As[128][36];
    __shared__ float Bs[128][36];
    int t = threadIdx.x;
    int lane = t & 31;
    int warp = t >> 5;
    int wm = warp & 3;          // 0..3  (M direction)
    int wn = warp >> 2;         // 0..1  (N direction)
    int g = lane >> 2;          // groupID 0..7
    int tg = lane & 3;          // tid-in-group 0..3
    int m0 = blockIdx.x * 128;
    int n0 = blockIdx.y * 128;

    float c[2][8][4];
#pragma unroll
    for (int mf = 0; mf < 2; mf++)
#pragma unroll
        for (int nf = 0; nf < 8; nf++)
#pragma unroll
            for (int k = 0; k < 4; k++) c[mf][nf][k] = 0.f;

    for (int kt = 0; kt < K; kt += 32) {
#pragma unroll
        for (int j = 0; j < 4; j++) {
            int idx = t + j * 256;
            int row = idx >> 3;
            int kq = idx & 7;
            const float* gp = A + (size_t)(m0 + row) * K + kt + kq * 4;
            float4 v = (m0 + row < M) ? *(const float4*)gp : make_float4(0.f, 0.f, 0.f, 0.f);
            uint4 u;
            asm("cvt.rna.tf32.f32 %0, %1;" : "=r"(u.x) : "f"(v.x));
            asm("cvt.rna.tf32.f32 %0, %1;" : "=r"(u.y) : "f"(v.y));
            asm("cvt.rna.tf32.f32 %0, %1;" : "=r"(u.z) : "f"(v.z));
            asm("cvt.rna.tf32.f32 %0, %1;" : "=r"(u.w) : "f"(v.w));
            *(uint4*)&As[row][kq * 4] = u;
            const float* gq = B + (size_t)(n0 + row) * K + kt + kq * 4;  // n0+row < 256 always
            float4 w = *(const float4*)gq;
            uint4 uw;
            asm("cvt.rna.tf32.f32 %0, %1;" : "=r"(uw.x) : "f"(w.x));
            asm("cvt.rna.tf32.f32 %0, %1;" : "=r"(uw.y) : "f"(w.y));
            asm("cvt.rna.tf32.f32 %0, %1;" : "=r"(uw.z) : "f"(w.z));
            asm("cvt.rna.tf32.f32 %0, %1;" : "=r"(uw.w) : "f"(w.w));
            *(uint4*)&Bs[row][kq * 4] = uw;
        }
        __syncthreads();

#pragma unroll
        for (int ks = 0; ks < 32; ks += 8) {
            uint32_t a[2][4], b[8][2];
#pragma unroll
            for (int mf = 0; mf < 2; mf++) {
                int r = wm * 32 + mf * 16 + g;
                a[mf][0] = __float_as_uint(As[r][ks + tg]);
                a[mf][1] = __float_as_uint(As[r + 8][ks + tg]);
                a[mf][2] = __float_as_uint(As[r][ks + tg + 4]);
                a[mf][3] = __float_as_uint(As[r + 8][ks + tg + 4]);
            }
#pragma unroll
            for (int nf = 0; nf < 8; nf++) {
                int col = wn * 64 + nf * 8 + g;
                b[nf][0] = __float_as_uint(Bs[col][ks + tg]);
                b[nf][1] = __float_as_uint(Bs[col][ks + tg + 4]);
            }
#pragma unroll
            for (int mf = 0; mf < 2; mf++)
#pragma unroll
                for (int nf = 0; nf < 8; nf++) {
                    asm volatile(
                        "mma.sync.aligned.m16n8k8.row.col.f32.tf32.tf32.f32 "
                        "{%0,%1,%2,%3}, {%4,%5,%6,%7}, {%8,%9}, {%0,%1,%2,%3};"
                        : "+f"(c[mf][nf][0]), "+f"(c[mf][nf][1]),
                          "+f"(c[mf][nf][2]), "+f"(c[mf][nf][3])
                        : "r"(a[mf][0]), "r"(a[mf][1]), "r"(a[mf][2]), "r"(a[mf][3]),
                          "r"(b[nf][0]), "r"(b[nf][1]));
                }
        }
        __syncthreads();
    }

#pragma unroll
    for (int mf = 0; mf < 2; mf++) {
        int r0 = m0 + wm * 32 + mf * 16 + g;
#pragma unroll
        for (int nf = 0; nf < 8; nf++) {
            int col = n0 + wn * 64 + nf * 8 + tg * 2;
            if (r0 < M) {
                *(float2*)(C + (size_t)r0 * FW + col) = make_float2(c[mf][nf][0], c[mf][nf][1]);
                CH[(size_t)r0 * (FW / 2) + (col >> 1)] = __floats2half2_rn(c[mf][nf][0], c[mf][nf][1]);
            }
            if (r0 + 8 < M) {
                *(float2*)(C + (size_t)(r0 + 8) * FW + col) = make_float2(c[mf][nf][2], c[mf][nf][3]);
                CH[(size_t)(r0 + 8) * (FW / 2) + (col >> 1)] = __floats2half2_rn(c[mf][nf][2], c[mf][nf][3]);
            }
        }
    }
}

// ---------------- el/er projection (warp per node, OUT=64) ----------------
__global__ void elr_kernel(const float* __restrict__ feat, const float* __restrict__ al,
                           const float* __restrict__ ar, float* __restrict__ el,
                           float* __restrict__ er) {
    int n = (blockIdx.x * blockDim.x + threadIdx.x) >> 5;
    int lane = threadIdx.x & 31;
    if (n >= NN) return;
    const float4* f = (const float4*)(feat + (size_t)n * FW) + lane * 2;
    const float4* a4 = (const float4*)al + lane * 2;
    const float4* r4 = (const float4*)ar + lane * 2;
    float4 f0 = f[0], f1 = f[1];
    float4 a0 = a4[0], a1 = a4[1];
    float4 b0 = r4[0], b1 = r4[1];
    float pl = f0.x * a0.x + f0.y * a0.y + f0.z * a0.z + f0.w * a0.w
             + f1.x * a1.x + f1.y * a1.y + f1.z * a1.z + f1.w * a1.w;
    float pr = f0.x * b0.x + f0.y * b0.y + f0.z * b0.z + f0.w * b0.w
             + f1.x * b1.x + f1.y * b1.y + f1.z * b1.z + f1.w * b1.w;
#pragma unroll
    for (int off = 4; off >= 1; off >>= 1) {
        pl += __shfl_xor_sync(0xffffffffu, pl, off);
        pr += __shfl_xor_sync(0xffffffffu, pr, off);
    }
    if ((lane & 7) == 0) {
        el[n * 4 + (lane >> 3)] = pl;
        er[n * 4 + (lane >> 3)] = pr;
    }
}

__device__ __forceinline__ float lrelu(float x) { return x >= 0.f ? x : NEG * x; }
__device__ __forceinline__ float comp4(float4 v, int i) {
    return i == 0 ? v.x : (i == 1 ? v.y : (i == 2 ? v.z : v.w));
}

// ---------------- aggregation, OUT=64 (layers 1-3): warp per dst node ----------------
// Single pass (no max-shift: logits are O(1), exp cannot overflow).
// Chunked: weights computed edge-parallel per 32-edge chunk, stashed in smem;
// serial loop only does the fp16 feature gather + FFMA.
__global__ void __launch_bounds__(256) agg64_kernel(const __half2* __restrict__ featH,
                                                    const float* __restrict__ el,
                                                    const float* __restrict__ er,
                                                    const float* __restrict__ resid,
                                                    const float* __restrict__ bias,
                                                    float* __restrict__ out) {
    __shared__ float4 s_ee[8][32];
    __shared__ int s_src[8][32];
    int warp = threadIdx.x >> 5;
    int n = (blockIdx.x * blockDim.x + threadIdx.x) >> 5;
    int lane = threadIdx.x & 31;
    if (n >= NN) return;
    int beg = g_rowstart[n], end = g_rowstart[n + 1];
    float4 erv = ((const float4*)er)[n];

    float acc[8];
#pragma unroll
    for (int k = 0; k < 8; k++) acc[k] = 0.f;
    float4 den = make_float4(0.f, 0.f, 0.f, 0.f);
    int hsel = lane >> 3;

    for (int c = beg; c < end; c += 32) {
        // phase a: edge-parallel weight computation
        int i = c + lane;
        float4 ee = make_float4(0.f, 0.f, 0.f, 0.f);
        int s = 0;
        if (i < end) {
            s = g_csrsrc[i];
            float4 e = ((const float4*)el)[s];
            ee.x = __expf(lrelu(e.x + erv.x));
            ee.y = __expf(lrelu(e.y + erv.y));
            ee.z = __expf(lrelu(e.z + erv.z));
            ee.w = __expf(lrelu(e.w + erv.w));
            den.x += ee.x; den.y += ee.y; den.z += ee.z; den.w += ee.w;
        }
        s_ee[warp][lane] = ee;
        s_src[warp][lane] = s;
        __syncwarp();
        // phase b: serial gather + accumulate
        int cnt = min(end - c, 32);
        const float* wsm = (const float*)&s_ee[warp][0];
        for (int j = 0; j < cnt; j++) {
            int sj = s_src[warp][j];
            float w = wsm[j * 4 + hsel];
            float4 hv = *(const float4*)(featH + (size_t)sj * (FW / 2) + lane * 4);
            float2 f0 = __half22float2(((const __half2*)&hv)[0]);
            float2 f1 = __half22float2(((const __half2*)&hv)[1]);
            float2 f2 = __half22float2(((const __half2*)&hv)[2]);
            float2 f3 = __half22float2(((const __half2*)&hv)[3]);
            acc[0] += w * f0.x; acc[1] += w * f0.y;
            acc[2] += w * f1.x; acc[3] += w * f1.y;
            acc[4] += w * f2.x; acc[5] += w * f2.y;
            acc[6] += w * f3.x; acc[7] += w * f3.y;
        }
        __syncwarp();
    }

    // warp-reduce denominators
#pragma unroll
    for (int off = 16; off >= 1; off >>= 1) {
        den.x += __shfl_xor_sync(0xffffffffu, den.x, off);
        den.y += __shfl_xor_sync(0xffffffffu, den.y, off);
        den.z += __shfl_xor_sync(0xffffffffu, den.z, off);
        den.w += __shfl_xor_sync(0xffffffffu, den.w, off);
    }
    float dh = comp4(den, hsel);
    float inv = (end > beg) ? 1.f / dh : 0.f;
    int base = n * FW + lane * 8;
    float o[8];
#pragma unroll
    for (int k = 0; k < 8; k++) {
        float v = acc[k] * inv + bias[lane * 8 + k];
        if (resid) v += resid[base + k];
        o[k] = v > 0.f ? v : (__expf(v) - 1.f);  // ELU
    }
    *(float4*)(out + base) = make_float4(o[0], o[1], o[2], o[3]);
    *(float4*)(out + base + 4) = make_float4(o[4], o[5], o[6], o[7]);
}

// ---------------- layer 4 GEMMs: feat4 = h*W4^T, res4 = h*resW4^T (NC=8) ----------------
__global__ void __launch_bounds__(256) gemm4_kernel(const float* __restrict__ A,
                                                    const float* __restrict__ W,
                                                    const float* __restrict__ R,
                                                    float* __restrict__ F,
                                                    float* __restrict__ Rv, int M) {
    __shared__ float sW[8 * 260];
    __shared__ float sR[8 * 260];
    int t = threadIdx.x;
    for (int i = t; i < 2048; i += 256) {
        int j = i >> 8, k = i & 255;
        sW[j * 260 + k] = W[i];
        sR[j * 260 + k] = R[i];
    }
    __syncthreads();
    int nl = t >> 3, j = t & 7;
    int n = blockIdx.x * 32 + nl;
    if (n >= M) return;
    const float4* a = (const float4*)(A + (size_t)n * 256);
    const float4* w = (const float4*)(sW + j * 260);
    const float4* r = (const float4*)(sR + j * 260);
    float s1 = 0.f, s2 = 0.f;
#pragma unroll 8
    for (int k = 0; k < 64; k++) {
        float4 av = a[k];
        float4 wv = w[k];
        float4 rv = r[k];
        s1 += av.x * wv.x + av.y * wv.y + av.z * wv.z + av.w * wv.w;
        s2 += av.x * rv.x + av.y * rv.y + av.z * rv.z + av.w * rv.w;
    }
    F[(size_t)n * 8 + j] = s1;
    Rv[(size_t)n * 8 + j] = s2;
}

__global__ void elr4_kernel(const float* __restrict__ feat4, const float* __restrict__ al4,
                            const float* __restrict__ ar4, float* __restrict__ el4,
                            float* __restrict__ er4) {
    int n = blockIdx.x * blockDim.x + threadIdx.x;
    if (n >= NN) return;
    float4 f0 = ((const float4*)feat4)[n * 2];
    float4 f1 = ((const float4*)feat4)[n * 2 + 1];
    float4 a0 = ((const float4*)al4)[0], a1 = ((const float4*)al4)[1];
    float4 r0 = ((const float4*)ar4)[0], r1 = ((const float4*)ar4)[1];
    float4 el, er;
    el.x = f0.x * a0.x + f0.y * a0.y;  er.x = f0.x * r0.x + f0.y * r0.y;
    el.y = f0.z * a0.z + f0.w * a0.w;  er.y = f0.z * r0.z + f0.w * r0.w;
    el.z = f1.x * a1.x + f1.y * a1.y;  er.z = f1.x * r1.x + f1.y * r1.y;
    el.w = f1.z * a1.z + f1.w * a1.w;  er.w = f1.z * r1.z + f1.w * r1.w;
    ((float4*)el4)[n] = el;
    ((float4*)er4)[n] = er;
}

// ---------------- layer 4 aggregation + softmax + head-mean (single pass) ----------------
__global__ void agg4_kernel(const float* __restrict__ feat4, const float* __restrict__ el4,
                            const float* __restrict__ er4, const float* __restrict__ res4,
                            const float* __restrict__ b4, float* __restrict__ out) {
    int n = (blockIdx.x * blockDim.x + threadIdx.x) >> 5;
    int lane = threadIdx.x & 31;
    if (n >= NN) return;
    int beg = g_rowstart[n], end = g_rowstart[n + 1];
    float4 erv = ((const float4*)er4)[n];

    float acc = 0.f;
    float4 den = make_float4(0.f, 0.f, 0.f, 0.f);
    int h = (lane >> 1) & 3;  // lane<8: lane = h*2 + c
    for (int i = beg; i < end; i++) {
        int s = g_csrsrc[i];
        float4 e = ((const float4*)el4)[s];
        float4 ee;
        ee.x = __expf(lrelu(e.x + erv.x));
        ee.y = __expf(lrelu(e.y + erv.y));
        ee.z = __expf(lrelu(e.z + erv.z));
        ee.w = __expf(lrelu(e.w + erv.w));
        den.x += ee.x; den.y += ee.y; den.z += ee.z; den.w += ee.w;
        if (lane < 8) acc += comp4(ee, h) * feat4[(size_t)s * 8 + lane];
    }

    float v = 0.f;
    if (lane < 8) {
        float dh = comp4(den, h);
        v = (end > beg ? acc / dh : 0.f) + res4[n * 8 + lane] + b4[lane];
    }
    float other = __shfl_xor_sync(0xffffffffu, v, 1);
    float mx = fmaxf(v, other);
    float ev = __expf(v - mx);
    float eo = __expf(other - mx);
    float sm = ev / (ev + eo);
    sm += __shfl_xor_sync(0xffffffffu, sm, 4);
    sm += __shfl_xor_sync(0xffffffffu, sm, 2);
    if (lane < 2) out[n * 2 + lane] = sm * 0.25f;
}

// ---------------- host ----------------
extern "C" void kernel_launch(void* const* d_in, const int* in_sizes, int n_in,
                              void* d_out, int out_size) {
    const float* x    = (const float*)d_in[0];
    const int*   src  = (const int*)d_in[1];
    const int*   dst  = (const int*)d_in[2];
    const float* W1   = (const float*)d_in[3];
    const float* al1  = (const float*)d_in[4];
    const float* ar1  = (const float*)d_in[5];
    const float* b1   = (const float*)d_in[6];
    const float* W2   = (const float*)d_in[7];
    const float* al2  = (const float*)d_in[8];
    const float* ar2  = (const float*)d_in[9];
    const float* b2   = (const float*)d_in[10];
    const float* W3   = (const float*)d_in[11];
    const float* al3  = (const float*)d_in[12];
    const float* ar3  = (const float*)d_in[13];
    const float* b3   = (const float*)d_in[14];
    const float* W4   = (const float*)d_in[15];
    const float* al4  = (const float*)d_in[16];
    const float* ar4  = (const float*)d_in[17];
    const float* b4   = (const float*)d_in[18];
    const float* rW4  = (const float*)d_in[19];
    float* out = (float*)d_out;

    void *p_feat, *p_featH, *p_bufA, *p_bufB, *p_el, *p_er, *p_f4, *p_r4, *p_el4, *p_er4;
    cudaGetSymbolAddress(&p_feat, g_feat);
    cudaGetSymbolAddress(&p_featH, g_featH);
    cudaGetSymbolAddress(&p_bufA, g_bufA);
    cudaGetSymbolAddress(&p_bufB, g_bufB);
    cudaGetSymbolAddress(&p_el, g_el);
    cudaGetSymbolAddress(&p_er, g_er);
    cudaGetSymbolAddress(&p_f4, g_feat4);
    cudaGetSymbolAddress(&p_r4, g_res4);
    cudaGetSymbolAddress(&p_el4, g_el4);
    cudaGetSymbolAddress(&p_er4, g_er4);
    float* feat = (float*)p_feat;
    __half2* featH = (__half2*)p_featH;
    float* bufA = (float*)p_bufA;
    float* bufB = (float*)p_bufB;
    float* el   = (float*)p_el;
    float* er   = (float*)p_er;
    float* f4   = (float*)p_f4;
    float* r4   = (float*)p_r4;
    float* el4  = (float*)p_el4;
    float* er4  = (float*)p_er4;

    const int TB = 256;
    int nodeBlocks = (NN + TB - 1) / TB;
    int edgeBlocks = (EE + TB - 1) / TB;
    int warpBlocks = (NN * 32 + TB - 1) / TB;  // warp-per-node kernels
    dim3 gemmGrid((NN + 127) / 128, 2);

    // --- CSR build (reused by all layers) ---
    zero_counts_kernel<<<nodeBlocks, TB>>>();
    hist_kernel<<<edgeBlocks, TB>>>(dst);
    scan_kernel<<<1, 1024>>>();
    scatter_kernel<<<edgeBlocks, TB>>>(src, dst);

    // --- layer 1: IN=128 -> 256, no residual ---
    gemm_tc_kernel<128><<<gemmGrid, TB>>>(x, W1, feat, featH, NN);
    elr_kernel<<<warpBlocks, TB>>>(feat, al1, ar1, el, er);
    agg64_kernel<<<warpBlocks, TB>>>(featH, el, er, nullptr, b1, bufA);

    // --- layer 2: 256 -> 256, identity residual ---
    gemm_tc_kernel<256><<<gemmGrid, TB>>>(bufA, W2, feat, featH, NN);
    elr_kernel<<<warpBlocks, TB>>>(feat, al2, ar2, el, er);
    agg64_kernel<<<warpBlocks, TB>>>(featH, el, er, bufA, b2, bufB);

    // --- layer 3: 256 -> 256, identity residual ---
    gemm_tc_kernel<256><<<gemmGrid, TB>>>(bufB, W3, feat, featH, NN);
    elr_kernel<<<warpBlocks, TB>>>(feat, al3, ar3, el, er);
    agg64_kernel<<<warpBlocks, TB>>>(featH, el, er, bufB, b3, bufA);

    // --- layer 4: 256 -> 8, fc residual, softmax + head-mean ---
    gemm4_kernel<<<(NN + 31) / 32, TB>>>(bufA, W4, rW4, f4, r4, NN);
    elr4_kernel<<<nodeBlocks, TB>>>(f4, al4, ar4, el4, er4);
    agg4_kernel<<<warpBlocks, TB>>>(f4, el4, er4, r4, b4, out);
}

// round 12
// speedup vs baseline: 1.5105x; 1.1115x over previous
#include <cuda_runtime.h>
#include <cuda_fp16.h>
#include <cstddef>
#include <cstdint>

#define NN 50000
#define EE 800000
#define HEADS 4
#define HIDD 64
#define FW 256      // HEADS*HIDD
#define NEG 0.2f

// ---------------- scratch (static device globals; no allocation) ----------------
__device__ __half2 g_featH[(size_t)NN * (FW / 2)];
__device__ float g_bufA[(size_t)NN * FW];
__device__ float g_bufB[(size_t)NN * FW];
__device__ float g_el[NN * 4];
__device__ float g_er[NN * 4];
__device__ float g_feat4[NN * 8];
__device__ float g_res4[NN * 8];
__device__ float g_el4[NN * 4];
__device__ float g_er4[NN * 4];
__device__ int g_count[NN];
__device__ int g_rowstart[NN + 1];
__device__ int g_rowfill[NN];
__device__ int g_csrsrc[EE];

// ---------------- CSR build ----------------
__global__ void zero_counts_kernel() {
    int i = blockIdx.x * blockDim.x + threadIdx.x;
    if (i < NN) g_count[i] = 0;
}

__global__ void hist_kernel(const int* __restrict__ dst) {
    int i = blockIdx.x * blockDim.x + threadIdx.x;
    if (i < EE) atomicAdd(&g_count[dst[i]], 1);
}

// shfl-based single-block scan (1024 threads)
__global__ void scan_kernel() {
    __shared__ int warpsum[32];
    __shared__ int carry;
    int t = threadIdx.x;
    int lane = t & 31, wid = t >> 5;
    if (t == 0) { carry = 0; g_rowstart[0] = 0; }
    __syncthreads();
    for (int base = 0; base < NN; base += 1024) {
        int i = base + t;
        int v = (i < NN) ? g_count[i] : 0;
        int x = v;
#pragma unroll
        for (int off = 1; off < 32; off <<= 1) {
            int y = __shfl_up_sync(0xffffffffu, x, off);
            if (lane >= off) x += y;
        }
        if (lane == 31) warpsum[wid] = x;
        __syncthreads();
        if (wid == 0) {
            int s = warpsum[lane];
#pragma unroll
            for (int off = 1; off < 32; off <<= 1) {
                int y = __shfl_up_sync(0xffffffffu, s, off);
                if (lane >= off) s += y;
            }
            warpsum[lane] = s;
        }
        __syncthreads();
        int incl = x + (wid ? warpsum[wid - 1] : 0) + carry;
        if (i < NN) {
            g_rowstart[i + 1] = incl;
            g_rowfill[i] = incl - v;
        }
        __syncthreads();
        if (t == 1023) carry = incl;
        __syncthreads();
    }
}

__global__ void scatter_kernel(const int* __restrict__ src, const int* __restrict__ dst) {
    int i = blockIdx.x * blockDim.x + threadIdx.x;
    if (i < EE) {
        int pos = atomicAdd(&g_rowfill[dst[i]], 1);
        g_csrsrc[pos] = src[i];
    }
}

// ---------------- tf32 tensor-core GEMM + fused el/er projection ----------------
// CH[M,256](fp16) = A[M,K] * B[256,K]^T ; el/er[M,4] computed in-epilogue.
// Each warp's wn selects one complete 64-col head, so el[n,head] is a
// warp-local reduction of the accumulator fragment against al/ar.
template<int K>
__global__ void __launch_bounds__(256, 2) gemm_tc_kernel(const float* __restrict__ A,
                                                         const float* __restrict__ B,
                                                         __half2* __restrict__ CH,
                                                         const float* __restrict__ al,
                                                         const float* __restrict__ ar,
                                                         float* __restrict__ el,
                                                         float* __restrict__ er, int M) {
    __shared__ float As[128][36];
    __shared__ float Bs[128][36];
    int t = threadIdx.x;
    int lane = t & 31;
    int warp = t >> 5;
    int wm = warp & 3;          // 0..3  (M direction)
    int wn = warp >> 2;         // 0..1  (N direction -> head within CTA half)
    int g = lane >> 2;          // groupID 0..7
    int tg = lane & 3;          // tid-in-group 0..3
    int m0 = blockIdx.x * 128;
    int n0 = blockIdx.y * 128;

    float c[2][8][4];
#pragma unroll
    for (int mf = 0; mf < 2; mf++)
#pragma unroll
        for (int nf = 0; nf < 8; nf++)
#pragma unroll
            for (int k = 0; k < 4; k++) c[mf][nf][k] = 0.f;

    for (int kt = 0; kt < K; kt += 32) {
#pragma unroll
        for (int j = 0; j < 4; j++) {
            int idx = t + j * 256;
            int row = idx >> 3;
            int kq = idx & 7;
            const float* gp = A + (size_t)(m0 + row) * K + kt + kq * 4;
            float4 v = (m0 + row < M) ? *(const float4*)gp : make_float4(0.f, 0.f, 0.f, 0.f);
            uint4 u;
            asm("cvt.rna.tf32.f32 %0, %1;" : "=r"(u.x) : "f"(v.x));
            asm("cvt.rna.tf32.f32 %0, %1;" : "=r"(u.y) : "f"(v.y));
            asm("cvt.rna.tf32.f32 %0, %1;" : "=r"(u.z) : "f"(v.z));
            asm("cvt.rna.tf32.f32 %0, %1;" : "=r"(u.w) : "f"(v.w));
            *(uint4*)&As[row][kq * 4] = u;
            const float* gq = B + (size_t)(n0 + row) * K + kt + kq * 4;  // n0+row < 256 always
            float4 w = *(const float4*)gq;
            uint4 uw;
            asm("cvt.rna.tf32.f32 %0, %1;" : "=r"(uw.x) : "f"(w.x));
            asm("cvt.rna.tf32.f32 %0, %1;" : "=r"(uw.y) : "f"(w.y));
            asm("cvt.rna.tf32.f32 %0, %1;" : "=r"(uw.z) : "f"(w.z));
            asm("cvt.rna.tf32.f32 %0, %1;" : "=r"(uw.w) : "f"(w.w));
            *(uint4*)&Bs[row][kq * 4] = uw;
        }
        __syncthreads();

#pragma unroll
        for (int ks = 0; ks < 32; ks += 8) {
            uint32_t a[2][4], b[8][2];
#pragma unroll
            for (int mf = 0; mf < 2; mf++) {
                int r = wm * 32 + mf * 16 + g;
                a[mf][0] = __float_as_uint(As[r][ks + tg]);
                a[mf][1] = __float_as_uint(As[r + 8][ks + tg]);
                a[mf][2] = __float_as_uint(As[r][ks + tg + 4]);
                a[mf][3] = __float_as_uint(As[r + 8][ks + tg + 4]);
            }
#pragma unroll
            for (int nf = 0; nf < 8; nf++) {
                int col = wn * 64 + nf * 8 + g;
                b[nf][0] = __float_as_uint(Bs[col][ks + tg]);
                b[nf][1] = __float_as_uint(Bs[col][ks + tg + 4]);
            }
#pragma unroll
            for (int mf = 0; mf < 2; mf++)
#pragma unroll
                for (int nf = 0; nf < 8; nf++) {
                    asm volatile(
                        "mma.sync.aligned.m16n8k8.row.col.f32.tf32.tf32.f32 "
                        "{%0,%1,%2,%3}, {%4,%5,%6,%7}, {%8,%9}, {%0,%1,%2,%3};"
                        : "+f"(c[mf][nf][0]), "+f"(c[mf][nf][1]),
                          "+f"(c[mf][nf][2]), "+f"(c[mf][nf][3])
                        : "r"(a[mf][0]), "r"(a[mf][1]), "r"(a[mf][2]), "r"(a[mf][3]),
                          "r"(b[nf][0]), "r"(b[nf][1]));
                }
        }
        __syncthreads();
    }

    // epilogue: fp16 feature store + fused el/er
    int head = blockIdx.y * 2 + wn;
    const float* alh = al + head * 64;
    const float* arh = ar + head * 64;
#pragma unroll
    for (int mf = 0; mf < 2; mf++) {
        int r0 = m0 + wm * 32 + mf * 16 + g;
        float pl0 = 0.f, pr0 = 0.f, pl8 = 0.f, pr8 = 0.f;
#pragma unroll
        for (int nf = 0; nf < 8; nf++) {
            int hc = nf * 8 + tg * 2;            // column within this head
            float2 av = *(const float2*)(alh + hc);
            float2 rv = *(const float2*)(arh + hc);
            pl0 += c[mf][nf][0] * av.x + c[mf][nf][1] * av.y;
            pr0 += c[mf][nf][0] * rv.x + c[mf][nf][1] * rv.y;
            pl8 += c[mf][nf][2] * av.x + c[mf][nf][3] * av.y;
            pr8 += c[mf][nf][2] * rv.x + c[mf][nf][3] * rv.y;
            int col = n0 + wn * 64 + hc;
            if (r0 < M)
                CH[(size_t)r0 * (FW / 2) + (col >> 1)] = __floats2half2_rn(c[mf][nf][0], c[mf][nf][1]);
            if (r0 + 8 < M)
                CH[(size_t)(r0 + 8) * (FW / 2) + (col >> 1)] = __floats2half2_rn(c[mf][nf][2], c[mf][nf][3]);
        }
        // reduce across the 4-lane tg group (lane = g*4 + tg; xor 1,2 stays in group)
#pragma unroll
        for (int off = 1; off <= 2; off <<= 1) {
            pl0 += __shfl_xor_sync(0xffffffffu, pl0, off);
            pr0 += __shfl_xor_sync(0xffffffffu, pr0, off);
            pl8 += __shfl_xor_sync(0xffffffffu, pl8, off);
            pr8 += __shfl_xor_sync(0xffffffffu, pr8, off);
        }
        if (tg == 0) {
            if (r0 < M) { el[r0 * 4 + head] = pl0; er[r0 * 4 + head] = pr0; }
            if (r0 + 8 < M) { el[(r0 + 8) * 4 + head] = pl8; er[(r0 + 8) * 4 + head] = pr8; }
        }
    }
}

__device__ __forceinline__ float lrelu(float x) { return x >= 0.f ? x : NEG * x; }
__device__ __forceinline__ float comp4(float4 v, int i) {
    return i == 0 ? v.x : (i == 1 ? v.y : (i == 2 ? v.z : v.w));
}

// ---------------- aggregation, OUT=64 (layers 1-3): warp per dst node ----------------
// Single pass (no max-shift: logits are O(1), exp cannot overflow).
__global__ void __launch_bounds__(256) agg64_kernel(const __half2* __restrict__ featH,
                                                    const float* __restrict__ el,
                                                    const float* __restrict__ er,
                                                    const float* __restrict__ resid,
                                                    const float* __restrict__ bias,
                                                    float* __restrict__ out) {
    __shared__ float4 s_ee[8][32];
    __shared__ int s_src[8][32];
    int warp = threadIdx.x >> 5;
    int n = (blockIdx.x * blockDim.x + threadIdx.x) >> 5;
    int lane = threadIdx.x & 31;
    if (n >= NN) return;
    int beg = g_rowstart[n], end = g_rowstart[n + 1];
    float4 erv = ((const float4*)er)[n];

    float acc[8];
#pragma unroll
    for (int k = 0; k < 8; k++) acc[k] = 0.f;
    float4 den = make_float4(0.f, 0.f, 0.f, 0.f);
    int hsel = lane >> 3;

    for (int c = beg; c < end; c += 32) {
        // phase a: edge-parallel weight computation
        int i = c + lane;
        float4 ee = make_float4(0.f, 0.f, 0.f, 0.f);
        int s = 0;
        if (i < end) {
            s = g_csrsrc[i];
            float4 e = ((const float4*)el)[s];
            ee.x = __expf(lrelu(e.x + erv.x));
            ee.y = __expf(lrelu(e.y + erv.y));
            ee.z = __expf(lrelu(e.z + erv.z));
            ee.w = __expf(lrelu(e.w + erv.w));
            den.x += ee.x; den.y += ee.y; den.z += ee.z; den.w += ee.w;
        }
        s_ee[warp][lane] = ee;
        s_src[warp][lane] = s;
        __syncwarp();
        // phase b: serial gather + accumulate
        int cnt = min(end - c, 32);
        const float* wsm = (const float*)&s_ee[warp][0];
        for (int j = 0; j < cnt; j++) {
            int sj = s_src[warp][j];
            float w = wsm[j * 4 + hsel];
            float4 hv = *(const float4*)(featH + (size_t)sj * (FW / 2) + lane * 4);
            float2 f0 = __half22float2(((const __half2*)&hv)[0]);
            float2 f1 = __half22float2(((const __half2*)&hv)[1]);
            float2 f2 = __half22float2(((const __half2*)&hv)[2]);
            float2 f3 = __half22float2(((const __half2*)&hv)[3]);
            acc[0] += w * f0.x; acc[1] += w * f0.y;
            acc[2] += w * f1.x; acc[3] += w * f1.y;
            acc[4] += w * f2.x; acc[5] += w * f2.y;
            acc[6] += w * f3.x; acc[7] += w * f3.y;
        }
        __syncwarp();
    }

    // warp-reduce denominators
#pragma unroll
    for (int off = 16; off >= 1; off >>= 1) {
        den.x += __shfl_xor_sync(0xffffffffu, den.x, off);
        den.y += __shfl_xor_sync(0xffffffffu, den.y, off);
        den.z += __shfl_xor_sync(0xffffffffu, den.z, off);
        den.w += __shfl_xor_sync(0xffffffffu, den.w, off);
    }
    float dh = comp4(den, hsel);
    float inv = (end > beg) ? 1.f / dh : 0.f;
    int base = n * FW + lane * 8;
    float o[8];
#pragma unroll
    for (int k = 0; k < 8; k++) {
        float v = acc[k] * inv + bias[lane * 8 + k];
        if (resid) v += resid[base + k];
        o[k] = v > 0.f ? v : (__expf(v) - 1.f);  // ELU
    }
    *(float4*)(out + base) = make_float4(o[0], o[1], o[2], o[3]);
    *(float4*)(out + base + 4) = make_float4(o[4], o[5], o[6], o[7]);
}

// ---------------- layer 4 GEMMs: feat4 = h*W4^T, res4 = h*resW4^T (NC=8) ----------------
__global__ void __launch_bounds__(256) gemm4_kernel(const float* __restrict__ A,
                                                    const float* __restrict__ W,
                                                    const float* __restrict__ R,
                                                    float* __restrict__ F,
                                                    float* __restrict__ Rv, int M) {
    __shared__ float sW[8 * 260];
    __shared__ float sR[8 * 260];
    int t = threadIdx.x;
    for (int i = t; i < 2048; i += 256) {
        int j = i >> 8, k = i & 255;
        sW[j * 260 + k] = W[i];
        sR[j * 260 + k] = R[i];
    }
    __syncthreads();
    int nl = t >> 3, j = t & 7;
    int n = blockIdx.x * 32 + nl;
    if (n >= M) return;
    const float4* a = (const float4*)(A + (size_t)n * 256);
    const float4* w = (const float4*)(sW + j * 260);
    const float4* r = (const float4*)(sR + j * 260);
    float s1 = 0.f, s2 = 0.f;
#pragma unroll 8
    for (int k = 0; k < 64; k++) {
        float4 av = a[k];
        float4 wv = w[k];
        float4 rv = r[k];
        s1 += av.x * wv.x + av.y * wv.y + av.z * wv.z + av.w * wv.w;
        s2 += av.x * rv.x + av.y * rv.y + av.z * rv.z + av.w * rv.w;
    }
    F[(size_t)n * 8 + j] = s1;
    Rv[(size_t)n * 8 + j] = s2;
}

__global__ void elr4_kernel(const float* __restrict__ feat4, const float* __restrict__ al4,
                            const float* __restrict__ ar4, float* __restrict__ el4,
                            float* __restrict__ er4) {
    int n = blockIdx.x * blockDim.x + threadIdx.x;
    if (n >= NN) return;
    float4 f0 = ((const float4*)feat4)[n * 2];
    float4 f1 = ((const float4*)feat4)[n * 2 + 1];
    float4 a0 = ((const float4*)al4)[0], a1 = ((const float4*)al4)[1];
    float4 r0 = ((const float4*)ar4)[0], r1 = ((const float4*)ar4)[1];
    float4 el, er;
    el.x = f0.x * a0.x + f0.y * a0.y;  er.x = f0.x * r0.x + f0.y * r0.y;
    el.y = f0.z * a0.z + f0.w * a0.w;  er.y = f0.z * r0.z + f0.w * r0.w;
    el.z = f1.x * a1.x + f1.y * a1.y;  er.z = f1.x * r1.x + f1.y * r1.y;
    el.w = f1.z * a1.z + f1.w * a1.w;  er.w = f1.z * r1.z + f1.w * r1.w;
    ((float4*)el4)[n] = el;
    ((float4*)er4)[n] = er;
}

// ---------------- layer 4 aggregation + softmax + head-mean (single pass) ----------------
__global__ void agg4_kernel(const float* __restrict__ feat4, const float* __restrict__ el4,
                            const float* __restrict__ er4, const float* __restrict__ res4,
                            const float* __restrict__ b4, float* __restrict__ out) {
    int n = (blockIdx.x * blockDim.x + threadIdx.x) >> 5;
    int lane = threadIdx.x & 31;
    if (n >= NN) return;
    int beg = g_rowstart[n], end = g_rowstart[n + 1];
    float4 erv = ((const float4*)er4)[n];

    float acc = 0.f;
    float4 den = make_float4(0.f, 0.f, 0.f, 0.f);
    int h = (lane >> 1) & 3;  // lane<8: lane = h*2 + c
    for (int i = beg; i < end; i++) {
        int s = g_csrsrc[i];
        float4 e = ((const float4*)el4)[s];
        float4 ee;
        ee.x = __expf(lrelu(e.x + erv.x));
        ee.y = __expf(lrelu(e.y + erv.y));
        ee.z = __expf(lrelu(e.z + erv.z));
        ee.w = __expf(lrelu(e.w + erv.w));
        den.x += ee.x; den.y += ee.y; den.z += ee.z; den.w += ee.w;
        if (lane < 8) acc += comp4(ee, h) * feat4[(size_t)s * 8 + lane];
    }

    float v = 0.f;
    if (lane < 8) {
        float dh = comp4(den, h);
        v = (end > beg ? acc / dh : 0.f) + res4[n * 8 + lane] + b4[lane];
    }
    float other = __shfl_xor_sync(0xffffffffu, v, 1);
    float mx = fmaxf(v, other);
    float ev = __expf(v - mx);
    float eo = __expf(other - mx);
    float sm = ev / (ev + eo);
    sm += __shfl_xor_sync(0xffffffffu, sm, 4);
    sm += __shfl_xor_sync(0xffffffffu, sm, 2);
    if (lane < 2) out[n * 2 + lane] = sm * 0.25f;
}

// ---------------- host ----------------
extern "C" void kernel_launch(void* const* d_in, const int* in_sizes, int n_in,
                              void* d_out, int out_size) {
    const float* x    = (const float*)d_in[0];
    const int*   src  = (const int*)d_in[1];
    const int*   dst  = (const int*)d_in[2];
    const float* W1   = (const float*)d_in[3];
    const float* al1  = (const float*)d_in[4];
    const float* ar1  = (const float*)d_in[5];
    const float* b1   = (const float*)d_in[6];
    const float* W2   = (const float*)d_in[7];
    const float* al2  = (const float*)d_in[8];
    const float* ar2  = (const float*)d_in[9];
    const float* b2   = (const float*)d_in[10];
    const float* W3   = (const float*)d_in[11];
    const float* al3  = (const float*)d_in[12];
    const float* ar3  = (const float*)d_in[13];
    const float* b3   = (const float*)d_in[14];
    const float* W4   = (const float*)d_in[15];
    const float* al4  = (const float*)d_in[16];
    const float* ar4  = (const float*)d_in[17];
    const float* b4   = (const float*)d_in[18];
    const float* rW4  = (const float*)d_in[19];
    float* out = (float*)d_out;

    void *p_featH, *p_bufA, *p_bufB, *p_el, *p_er, *p_f4, *p_r4, *p_el4, *p_er4;
    cudaGetSymbolAddress(&p_featH, g_featH);
    cudaGetSymbolAddress(&p_bufA, g_bufA);
    cudaGetSymbolAddress(&p_bufB, g_bufB);
    cudaGetSymbolAddress(&p_el, g_el);
    cudaGetSymbolAddress(&p_er, g_er);
    cudaGetSymbolAddress(&p_f4, g_feat4);
    cudaGetSymbolAddress(&p_r4, g_res4);
    cudaGetSymbolAddress(&p_el4, g_el4);
    cudaGetSymbolAddress(&p_er4, g_er4);
    __half2* featH = (__half2*)p_featH;
    float* bufA = (float*)p_bufA;
    float* bufB = (float*)p_bufB;
    float* el   = (float*)p_el;
    float* er   = (float*)p_er;
    float* f4   = (float*)p_f4;
    float* r4   = (float*)p_r4;
    float* el4  = (float*)p_el4;
    float* er4  = (float*)p_er4;

    const int TB = 256;
    int nodeBlocks = (NN + TB - 1) / TB;
    int edgeBlocks = (EE + TB - 1) / TB;
    int warpBlocks = (NN * 32 + TB - 1) / TB;  // warp-per-node kernels
    dim3 gemmGrid((NN + 127) / 128, 2);

    // --- CSR build (reused by all layers) ---
    zero_counts_kernel<<<nodeBlocks, TB>>>();
    hist_kernel<<<edgeBlocks, TB>>>(dst);
    scan_kernel<<<1, 1024>>>();
    scatter_kernel<<<edgeBlocks, TB>>>(src, dst);

    // --- layer 1: IN=128 -> 256, no residual ---
    gemm_tc_kernel<128><<<gemmGrid, TB>>>(x, W1, featH, al1, ar1, el, er, NN);
    agg64_kernel<<<warpBlocks, TB>>>(featH, el, er, nullptr, b1, bufA);

    // --- layer 2: 256 -> 256, identity residual ---
    gemm_tc_kernel<256><<<gemmGrid, TB>>>(bufA, W2, featH, al2, ar2, el, er, NN);
    agg64_kernel<<<warpBlocks, TB>>>(featH, el, er, bufA, b2, bufB);

    // --- layer 3: 256 -> 256, identity residual ---
    gemm_tc_kernel<256><<<gemmGrid, TB>>>(bufB, W3, featH, al3, ar3, el, er, NN);
    agg64_kernel<<<warpBlocks, TB>>>(featH, el, er, bufB, b3, bufA);

    // --- layer 4: 256 -> 8, fc residual, softmax + head-mean ---
    gemm4_kernel<<<(NN + 31) / 32, TB>>>(bufA, W4, rW4, f4, r4, NN);
    elr4_kernel<<<nodeBlocks, TB>>>(f4, al4, ar4, el4, er4);
    agg4_kernel<<<warpBlocks, TB>>>(f4, el4, er4, r4, b4, out);
}